// round 4
// baseline (speedup 1.0000x reference)
#include <cuda_runtime.h>

#define NL 4
#define TPB 256

typedef unsigned long long u64;

// ---- packed 2x f32 (Blackwell f32x2 pipe) ----
struct p2 { u64 v; };

__device__ __forceinline__ p2 mk2(float lo, float hi) {
    p2 r; asm("mov.b64 %0, {%1,%2};" : "=l"(r.v) : "f"(lo), "f"(hi)); return r;
}
__device__ __forceinline__ void un2(p2 a, float& lo, float& hi) {
    asm("mov.b64 {%0,%1}, %2;" : "=f"(lo), "=f"(hi) : "l"(a.v));
}
__device__ __forceinline__ p2 fma2(p2 a, p2 b, p2 c) {
    p2 r; asm("fma.rn.f32x2 %0, %1, %2, %3;" : "=l"(r.v) : "l"(a.v), "l"(b.v), "l"(c.v)); return r;
}
__device__ __forceinline__ p2 mul2(p2 a, p2 b) {
    p2 r; asm("mul.rn.f32x2 %0, %1, %2;" : "=l"(r.v) : "l"(a.v), "l"(b.v)); return r;
}
__device__ __forceinline__ p2 add2(p2 a, p2 b) {
    p2 r; asm("add.rn.f32x2 %0, %1, %2;" : "=l"(r.v) : "l"(a.v), "l"(b.v)); return r;
}
__device__ __forceinline__ p2 neg2(p2 a) { p2 r; r.v = a.v ^ 0x8000000080000000ULL; return r; }

__device__ __forceinline__ float fast_tanh(float v) {
    float r; asm("tanh.approx.f32 %0, %1;" : "=f"(r) : "f"(v)); return r;
}

// RX: na = c*a + s*(i-swapped b); packed across 2 samples, ns = -s.
__device__ __forceinline__ void apply_rx(p2 c, p2 s, p2 ns,
                                         p2& ax, p2& ay, p2& bx, p2& by) {
    p2 nax = fma2(c, ax, mul2(s,  by));
    p2 nay = fma2(c, ay, mul2(ns, bx));
    p2 nbx = fma2(c, bx, mul2(s,  ay));
    p2 nby = fma2(c, by, mul2(ns, ax));
    ax = nax; ay = nay; bx = nbx; by = nby;
}

// SU(2) rot: R = [[a, b], [-conj(b), conj(a)]], 7 pre-negated packed scalars.
__device__ __forceinline__ void apply_rot(p2 ar, p2 ai, p2 nai,
                                          p2 br, p2 nbr, p2 bi, p2 nbi,
                                          p2& ax, p2& ay, p2& bx, p2& by) {
    p2 nax = fma2(nbi, by, fma2(br,  bx, fma2(nai, ay, mul2(ar,  ax))));
    p2 nay = fma2(bi,  bx, fma2(br,  by, fma2(ai,  ax, mul2(ar,  ay))));
    p2 nbx = fma2(ai,  by, fma2(ar,  bx, fma2(nbi, ay, mul2(nbr, ax))));
    p2 nby = fma2(nai, bx, fma2(ar,  by, fma2(bi,  ax, mul2(nbr, ay))));
    ax = nax; ay = nay; bx = nbx; by = nby;
}

__global__ __launch_bounds__(TPB) void hybrid_qnn_kernel(
    const float4* __restrict__ x4,
    const float* __restrict__ w1, const float* __restrict__ b1,
    const float* __restrict__ w2, const float* __restrict__ b2,
    const float* __restrict__ qw,
    const float* __restrict__ pw, const float* __restrict__ pb,
    float2* __restrict__ out2, int B2)
{
    // sP: duplicated packed params. [0:8) w1, [8:12) b1, [12:20) w2,
    //     [20:22) b2, [22:24) post_w, [24] post_b
    __shared__ float2 sP[25];
    // sR[m][k]: matrix m = l*2+wire, k: 0=ar 1=ai 2=-ai 3=br 4=-br 5=bi 6=-bi
    __shared__ float2 sR[NL * 2][8];

    int tid = threadIdx.x;

    if (tid < 25) {
        float v;
        if (tid < 8)       v = w1[tid];
        else if (tid < 12) v = b1[tid - 8];
        else if (tid < 20) v = w2[tid - 12];
        else if (tid < 22) v = b2[tid - 20];
        else if (tid < 24) v = pw[tid - 22];
        else               v = pb[0];
        sP[tid] = make_float2(v, v);
    }

    // 8 threads of warp 1 each build one SU(2) matrix (batch-invariant)
    if (tid >= 32 && tid < 40) {
        int m = tid - 32;
        const float* q = qw + m * 3;
        float phi = q[0], th = q[1], om = q[2];
        float st, ct, sp, cp, sm, cm;
        sincosf(0.5f * th, &st, &ct);
        sincosf(0.5f * (phi + om), &sp, &cp);
        sincosf(0.5f * (phi - om), &sm, &cm);
        float ar =  cp * ct, ai = -sp * ct;   // r00 = ep * c
        float br = -cm * st, bi = -sm * st;   // r01 = -conj(em) * s
        sR[m][0] = make_float2(ar, ar);
        sR[m][1] = make_float2(ai, ai);
        sR[m][2] = make_float2(-ai, -ai);
        sR[m][3] = make_float2(br, br);
        sR[m][4] = make_float2(-br, -br);
        sR[m][5] = make_float2(bi, bi);
        sR[m][6] = make_float2(-bi, -bi);
    }
    __syncthreads();

    int i = blockIdx.x * TPB + tid;
    if (i >= B2) return;

    const p2* P = reinterpret_cast<const p2*>(sP);

    // two samples: 2i and 2i+1
    float4 xv = x4[i];
    p2 X0 = mk2(xv.x, xv.z);
    p2 X1 = mk2(xv.y, xv.w);

    // ---- pre-net (packed FMAs, scalar tanh) ----
    float lo, hi;
    p2 h[4];
#pragma unroll
    for (int j = 0; j < 4; j++) {
        p2 t = fma2(P[2*j], X0, fma2(P[2*j+1], X1, P[8+j]));
        un2(t, lo, hi);
        h[j] = mk2(fast_tanh(lo), fast_tanh(hi));
    }
    p2 t0 = fma2(P[12], h[0], fma2(P[13], h[1], fma2(P[14], h[2], fma2(P[15], h[3], P[20]))));
    p2 t1 = fma2(P[16], h[0], fma2(P[17], h[1], fma2(P[18], h[2], fma2(P[19], h[3], P[21]))));

    float a0l, a0h, a1l, a1h;
    un2(t0, a0l, a0h); un2(t1, a1l, a1h);
    a0l = fast_tanh(a0l); a0h = fast_tanh(a0h);
    a1l = fast_tanh(a1l); a1h = fast_tanh(a1h);

    float sl, cl, sh, ch;
    __sincosf(0.5f * a0l, &sl, &cl); __sincosf(0.5f * a0h, &sh, &ch);
    p2 c0 = mk2(cl, ch), s0 = mk2(sl, sh);
    __sincosf(0.5f * a1l, &sl, &cl); __sincosf(0.5f * a1h, &sh, &ch);
    p2 c1 = mk2(cl, ch), s1 = mk2(sl, sh);
    p2 ns0 = neg2(s0), ns1 = neg2(s1);

    // ---- quantum state: amplitudes s[q0][q1], re/im packed across 2 samples ----
    p2 one = mk2(1.f, 1.f), zero; zero.v = 0ULL;
    p2 s00x = one,  s00y = zero;
    p2 s01x = zero, s01y = zero;
    p2 s10x = zero, s10y = zero;
    p2 s11x = zero, s11y = zero;

#pragma unroll
    for (int l = 0; l < NL; l++) {
        // AngleEmbedding: RX(a0) on qubit0, RX(a1) on qubit1
        apply_rx(c0, s0, ns0, s00x, s00y, s10x, s10y);
        apply_rx(c0, s0, ns0, s01x, s01y, s11x, s11y);
        apply_rx(c1, s1, ns1, s00x, s00y, s01x, s01y);
        apply_rx(c1, s1, ns1, s10x, s10y, s11x, s11y);
        // Rot wire 0
        {
            const p2* M = reinterpret_cast<const p2*>(sR[l * 2 + 0]);
            p2 ar = M[0], ai = M[1], nai = M[2], br = M[3], nbr = M[4], bi = M[5], nbi = M[6];
            apply_rot(ar, ai, nai, br, nbr, bi, nbi, s00x, s00y, s10x, s10y);
            apply_rot(ar, ai, nai, br, nbr, bi, nbi, s01x, s01y, s11x, s11y);
        }
        // Rot wire 1
        {
            const p2* M = reinterpret_cast<const p2*>(sR[l * 2 + 1]);
            p2 ar = M[0], ai = M[1], nai = M[2], br = M[3], nbr = M[4], bi = M[5], nbi = M[6];
            apply_rot(ar, ai, nai, br, nbr, bi, nbi, s00x, s00y, s01x, s01y);
            apply_rot(ar, ai, nai, br, nbr, bi, nbi, s10x, s10y, s11x, s11y);
        }
        // CNOT(0,1): swap s10 <-> s11 ; CNOT(1,0): swap s01 <-> s11
        p2 tx = s10x, ty = s10y; s10x = s11x; s10y = s11y; s11x = tx; s11y = ty;
        tx = s01x; ty = s01y; s01x = s11x; s01y = s11y; s11x = tx; s11y = ty;
    }

    // ---- measurement; unitarity => q0 = p00+p01, q1 = p00+p10 ----
    p2 m00 = fma2(s00y, s00y, mul2(s00x, s00x));
    p2 q0 = fma2(s01y, s01y, fma2(s01x, s01x, m00));
    p2 q1 = fma2(s10y, s10y, fma2(s10x, s10x, m00));

    p2 y = fma2(P[22], q0, fma2(P[23], q1, P[24]));
    float yl, yh;
    un2(y, yl, yh);
    // sigmoid(y) = 0.5*tanh(y/2) + 0.5
    float o0 = fmaf(0.5f, fast_tanh(0.5f * yl), 0.5f);
    float o1 = fmaf(0.5f, fast_tanh(0.5f * yh), 0.5f);
    out2[i] = make_float2(o0, o1);
}

extern "C" void kernel_launch(void* const* d_in, const int* in_sizes, int n_in,
                              void* d_out, int out_size) {
    const float4* x  = (const float4*)d_in[0];
    const float* w1  = (const float*)d_in[1];
    const float* b1  = (const float*)d_in[2];
    const float* w2  = (const float*)d_in[3];
    const float* b2  = (const float*)d_in[4];
    const float* qw  = (const float*)d_in[5];
    const float* pw  = (const float*)d_in[6];
    const float* pb  = (const float*)d_in[7];
    float2* out = (float2*)d_out;

    int B2 = in_sizes[0] / 4;  // two samples per thread
    int grid = (B2 + TPB - 1) / TPB;
    hybrid_qnn_kernel<<<grid, TPB>>>(x, w1, b1, w2, b2, qw, pw, pb, out, B2);
}

// round 5
// speedup vs baseline: 1.0935x; 1.0935x over previous
#include <cuda_runtime.h>

#define NL 4
#define TPB 128

typedef unsigned long long u64;

// ---- packed 2x f32 (Blackwell f32x2 pipe) ----
struct p2 { u64 v; };

__device__ __forceinline__ p2 mk2(float lo, float hi) {
    p2 r; asm("mov.b64 %0, {%1,%2};" : "=l"(r.v) : "f"(lo), "f"(hi)); return r;
}
__device__ __forceinline__ void un2(p2 a, float& lo, float& hi) {
    asm("mov.b64 {%0,%1}, %2;" : "=f"(lo), "=f"(hi) : "l"(a.v));
}
__device__ __forceinline__ p2 fma2(p2 a, p2 b, p2 c) {
    p2 r; asm("fma.rn.f32x2 %0, %1, %2, %3;" : "=l"(r.v) : "l"(a.v), "l"(b.v), "l"(c.v)); return r;
}
__device__ __forceinline__ p2 mul2(p2 a, p2 b) {
    p2 r; asm("mul.rn.f32x2 %0, %1, %2;" : "=l"(r.v) : "l"(a.v), "l"(b.v)); return r;
}
__device__ __forceinline__ p2 neg2(p2 a) { p2 r; r.v = a.v ^ 0x8000000080000000ULL; return r; }

__device__ __forceinline__ float fast_tanh(float v) {
    float r; asm("tanh.approx.f32 %0, %1;" : "=f"(r) : "f"(v)); return r;
}

// SU(2) apply: R = [[a, b], [-conj(b), conj(a)]], pre-negated components given.
__device__ __forceinline__ void apply_rot(p2 ar, p2 ai, p2 nai,
                                          p2 br, p2 nbr, p2 bi, p2 nbi,
                                          p2& ax, p2& ay, p2& bx, p2& by) {
    p2 nax = fma2(nbi, by, fma2(br,  bx, fma2(nai, ay, mul2(ar,  ax))));
    p2 nay = fma2(bi,  bx, fma2(br,  by, fma2(ai,  ax, mul2(ar,  ay))));
    p2 nbx = fma2(ai,  by, fma2(ar,  bx, fma2(nbi, ay, mul2(nbr, ax))));
    p2 nby = fma2(nai, bx, fma2(ar,  by, fma2(bi,  ax, mul2(nbr, ay))));
    ax = nax; ay = nay; bx = nbx; by = nby;
}

__global__ __launch_bounds__(TPB) void hybrid_qnn_kernel(
    const float4* __restrict__ x4,
    const float* __restrict__ w1, const float* __restrict__ b1,
    const float* __restrict__ w2, const float* __restrict__ b2,
    const float* __restrict__ qw,
    const float* __restrict__ pw, const float* __restrict__ pb,
    float4* __restrict__ out4, int B4)
{
    // sP: duplicated packed params. [0:8) w1, [8:12) b1, [12:20) w2,
    //     [20:22) b2, [22:24) post_w, [24] post_b
    __shared__ float2 sP[25];
    // sR[m][k]: matrix m = l*2+wire; k: 0=ar 1=ai 2=-ai 3=br 4=-br 5=bi 6=-bi 7=-ar
    __shared__ float2 sR[NL * 2][8];

    int tid = threadIdx.x;

    if (tid < 25) {
        float v;
        if (tid < 8)       v = w1[tid];
        else if (tid < 12) v = b1[tid - 8];
        else if (tid < 20) v = w2[tid - 12];
        else if (tid < 22) v = b2[tid - 20];
        else if (tid < 24) v = pw[tid - 22];
        else               v = pb[0];
        sP[tid] = make_float2(v, v);
    }

    // 8 threads of warp 1 each build one SU(2) matrix (batch-invariant)
    if (tid >= 32 && tid < 40) {
        int m = tid - 32;
        const float* q = qw + m * 3;
        float phi = q[0], th = q[1], om = q[2];
        float st, ct, sp, cp, sm, cm;
        sincosf(0.5f * th, &st, &ct);
        sincosf(0.5f * (phi + om), &sp, &cp);
        sincosf(0.5f * (phi - om), &sm, &cm);
        float ar =  cp * ct, ai = -sp * ct;   // r00 = ep * c
        float br = -cm * st, bi = -sm * st;   // r01 = -conj(em) * s
        sR[m][0] = make_float2(ar, ar);
        sR[m][1] = make_float2(ai, ai);
        sR[m][2] = make_float2(-ai, -ai);
        sR[m][3] = make_float2(br, br);
        sR[m][4] = make_float2(-br, -br);
        sR[m][5] = make_float2(bi, bi);
        sR[m][6] = make_float2(-bi, -bi);
        sR[m][7] = make_float2(-ar, -ar);
    }
    __syncthreads();

    int i = blockIdx.x * TPB + tid;
    if (i >= B4) return;

    const p2* P = reinterpret_cast<const p2*>(sP);

    // ---- 4 samples per thread: 2 independent packed chains ----
    p2 c0[2], s0[2], c1[2], s1[2];
#pragma unroll
    for (int ch = 0; ch < 2; ch++) {
        float4 xv = x4[2 * i + ch];
        p2 X0 = mk2(xv.x, xv.z);
        p2 X1 = mk2(xv.y, xv.w);

        float lo, hi;
        p2 h[4];
#pragma unroll
        for (int j = 0; j < 4; j++) {
            p2 t = fma2(P[2*j], X0, fma2(P[2*j+1], X1, P[8+j]));
            un2(t, lo, hi);
            h[j] = mk2(fast_tanh(lo), fast_tanh(hi));
        }
        p2 t0 = fma2(P[12], h[0], fma2(P[13], h[1], fma2(P[14], h[2], fma2(P[15], h[3], P[20]))));
        p2 t1 = fma2(P[16], h[0], fma2(P[17], h[1], fma2(P[18], h[2], fma2(P[19], h[3], P[21]))));

        float a0l, a0h, a1l, a1h;
        un2(t0, a0l, a0h); un2(t1, a1l, a1h);
        a0l = fast_tanh(a0l); a0h = fast_tanh(a0h);
        a1l = fast_tanh(a1l); a1h = fast_tanh(a1h);

        float sl, cl, sh, chh;
        __sincosf(0.5f * a0l, &sl, &cl); __sincosf(0.5f * a0h, &sh, &chh);
        c0[ch] = mk2(cl, chh); s0[ch] = mk2(sl, sh);
        __sincosf(0.5f * a1l, &sl, &cl); __sincosf(0.5f * a1h, &sh, &chh);
        c1[ch] = mk2(cl, chh); s1[ch] = mk2(sl, sh);
    }

    // state amplitudes s[q0][q1], re/im packed; [chain][component]
    p2 one = mk2(1.f, 1.f), zero; zero.v = 0ULL;
    p2 s00x[2], s00y[2], s01x[2], s01y[2], s10x[2], s10y[2], s11x[2], s11y[2];
#pragma unroll
    for (int ch = 0; ch < 2; ch++) {
        s00x[ch] = one;  s00y[ch] = zero;
        s01x[ch] = zero; s01y[ch] = zero;
        s10x[ch] = zero; s10y[ch] = zero;
        s11x[ch] = zero; s11y[ch] = zero;
    }

#pragma unroll
    for (int l = 0; l < NL; l++) {
        // ---- wire 0: G = R_l0 * RX(a0), applied to pairs (s00,s10), (s01,s11) ----
        {
            const p2* M = reinterpret_cast<const p2*>(sR[l * 2 + 0]);
            p2 Mar = M[0], Mai = M[1], Mbr = M[3], Mnbr = M[4], Mbi = M[5], Mnar = M[7];
#pragma unroll
            for (int ch = 0; ch < 2; ch++) {
                p2 gar = fma2(Mar, c0[ch], mul2(Mbi,  s0[ch]));  // ar*c + bi*s
                p2 gai = fma2(Mai, c0[ch], mul2(Mnbr, s0[ch]));  // ai*c - br*s
                p2 gbr = fma2(Mai, s0[ch], mul2(Mbr,  c0[ch]));  // ai*s + br*c
                p2 gbi = fma2(Mbi, c0[ch], mul2(Mnar, s0[ch]));  // bi*c - ar*s
                p2 ngai = neg2(gai), ngbr = neg2(gbr), ngbi = neg2(gbi);
                apply_rot(gar, gai, ngai, gbr, ngbr, gbi, ngbi,
                          s00x[ch], s00y[ch], s10x[ch], s10y[ch]);
                apply_rot(gar, gai, ngai, gbr, ngbr, gbi, ngbi,
                          s01x[ch], s01y[ch], s11x[ch], s11y[ch]);
            }
        }
        // ---- wire 1: G = R_l1 * RX(a1), applied to pairs (s00,s01), (s10,s11) ----
        {
            const p2* M = reinterpret_cast<const p2*>(sR[l * 2 + 1]);
            p2 Mar = M[0], Mai = M[1], Mbr = M[3], Mnbr = M[4], Mbi = M[5], Mnar = M[7];
#pragma unroll
            for (int ch = 0; ch < 2; ch++) {
                p2 gar = fma2(Mar, c1[ch], mul2(Mbi,  s1[ch]));
                p2 gai = fma2(Mai, c1[ch], mul2(Mnbr, s1[ch]));
                p2 gbr = fma2(Mai, s1[ch], mul2(Mbr,  c1[ch]));
                p2 gbi = fma2(Mbi, c1[ch], mul2(Mnar, s1[ch]));
                p2 ngai = neg2(gai), ngbr = neg2(gbr), ngbi = neg2(gbi);
                apply_rot(gar, gai, ngai, gbr, ngbr, gbi, ngbi,
                          s00x[ch], s00y[ch], s01x[ch], s01y[ch]);
                apply_rot(gar, gai, ngai, gbr, ngbr, gbi, ngbi,
                          s10x[ch], s10y[ch], s11x[ch], s11y[ch]);
            }
        }
        // CNOT(0,1): swap s10 <-> s11 ; CNOT(1,0): swap s01 <-> s11
#pragma unroll
        for (int ch = 0; ch < 2; ch++) {
            p2 tx = s10x[ch], ty = s10y[ch];
            s10x[ch] = s11x[ch]; s10y[ch] = s11y[ch]; s11x[ch] = tx; s11y[ch] = ty;
            tx = s01x[ch]; ty = s01y[ch];
            s01x[ch] = s11x[ch]; s01y[ch] = s11y[ch]; s11x[ch] = tx; s11y[ch] = ty;
        }
    }

    // ---- measurement; unitarity => q0 = p00+p01, q1 = p00+p10 ----
    float o[4];
#pragma unroll
    for (int ch = 0; ch < 2; ch++) {
        p2 m00 = fma2(s00y[ch], s00y[ch], mul2(s00x[ch], s00x[ch]));
        p2 q0 = fma2(s01y[ch], s01y[ch], fma2(s01x[ch], s01x[ch], m00));
        p2 q1 = fma2(s10y[ch], s10y[ch], fma2(s10x[ch], s10x[ch], m00));
        p2 y = fma2(P[22], q0, fma2(P[23], q1, P[24]));
        float yl, yh;
        un2(y, yl, yh);
        // sigmoid(y) = 0.5*tanh(y/2) + 0.5
        o[2*ch]   = fmaf(0.5f, fast_tanh(0.5f * yl), 0.5f);
        o[2*ch+1] = fmaf(0.5f, fast_tanh(0.5f * yh), 0.5f);
    }
    out4[i] = make_float4(o[0], o[1], o[2], o[3]);
}

extern "C" void kernel_launch(void* const* d_in, const int* in_sizes, int n_in,
                              void* d_out, int out_size) {
    const float4* x  = (const float4*)d_in[0];
    const float* w1  = (const float*)d_in[1];
    const float* b1  = (const float*)d_in[2];
    const float* w2  = (const float*)d_in[3];
    const float* b2  = (const float*)d_in[4];
    const float* qw  = (const float*)d_in[5];
    const float* pw  = (const float*)d_in[6];
    const float* pb  = (const float*)d_in[7];
    float4* out = (float4*)d_out;

    int B4 = in_sizes[0] / 8;  // four samples per thread
    int grid = (B4 + TPB - 1) / TPB;
    hybrid_qnn_kernel<<<grid, TPB>>>(x, w1, b1, w2, b2, qw, pw, pb, out, B4);
}

// round 6
// speedup vs baseline: 1.1083x; 1.0135x over previous
#include <cuda_runtime.h>

#define NL 4
#define TPB 128

typedef unsigned long long u64;

// ---- packed 2x f32 (Blackwell f32x2 pipe) ----
struct p2 { u64 v; };

__device__ __forceinline__ p2 mk2(float lo, float hi) {
    p2 r; asm("mov.b64 %0, {%1,%2};" : "=l"(r.v) : "f"(lo), "f"(hi)); return r;
}
__device__ __forceinline__ void un2(p2 a, float& lo, float& hi) {
    asm("mov.b64 {%0,%1}, %2;" : "=f"(lo), "=f"(hi) : "l"(a.v));
}
__device__ __forceinline__ p2 fma2(p2 a, p2 b, p2 c) {
    p2 r; asm("fma.rn.f32x2 %0, %1, %2, %3;" : "=l"(r.v) : "l"(a.v), "l"(b.v), "l"(c.v)); return r;
}
__device__ __forceinline__ p2 mul2(p2 a, p2 b) {
    p2 r; asm("mul.rn.f32x2 %0, %1, %2;" : "=l"(r.v) : "l"(a.v), "l"(b.v)); return r;
}
__device__ __forceinline__ p2 neg2(p2 a) { p2 r; r.v = a.v ^ 0x8000000080000000ULL; return r; }

__device__ __forceinline__ float fast_tanh(float v) {
    float r; asm("tanh.approx.f32 %0, %1;" : "=f"(r) : "f"(v)); return r;
}

// ---- batch-invariant data: staged by setup kernel, then copied to __constant__ ----
// layout (float2, both lanes equal):
// [0:25)  params: 0-7 w1, 8-11 b1, 12-19 w2, 20-21 b2, 22-23 post_w, 24 post_b
// [25+m*8+k] matrix m = layer*2+wire; k: 0=ar 1=ai 2=-ai 3=br 4=-br 5=bi 6=-bi 7=-ar
__device__ float2 gStage[89];
__constant__ float2 cC[89];

__global__ void setup_kernel(const float* __restrict__ w1, const float* __restrict__ b1,
                             const float* __restrict__ w2, const float* __restrict__ b2,
                             const float* __restrict__ qw,
                             const float* __restrict__ pw, const float* __restrict__ pb) {
    int tid = threadIdx.x;
    if (tid < 25) {
        float v;
        if (tid < 8)       v = w1[tid];
        else if (tid < 12) v = b1[tid - 8];
        else if (tid < 20) v = w2[tid - 12];
        else if (tid < 22) v = b2[tid - 20];
        else if (tid < 24) v = pw[tid - 22];
        else               v = pb[0];
        gStage[tid] = make_float2(v, v);
    }
    if (tid >= 32 && tid < 40) {
        int m = tid - 32;
        const float* q = qw + m * 3;
        float phi = q[0], th = q[1], om = q[2];
        float st, ct, sp, cp, sm, cm;
        sincosf(0.5f * th, &st, &ct);
        sincosf(0.5f * (phi + om), &sp, &cp);
        sincosf(0.5f * (phi - om), &sm, &cm);
        float ar =  cp * ct, ai = -sp * ct;   // r00 = ep * c
        float br = -cm * st, bi = -sm * st;   // r01 = -conj(em) * s
        float2* R = &gStage[25 + m * 8];
        R[0] = make_float2(ar, ar);
        R[1] = make_float2(ai, ai);
        R[2] = make_float2(-ai, -ai);
        R[3] = make_float2(br, br);
        R[4] = make_float2(-br, -br);
        R[5] = make_float2(bi, bi);
        R[6] = make_float2(-bi, -bi);
        R[7] = make_float2(-ar, -ar);
    }
}

__device__ __forceinline__ p2 ldc(int i) {
    float2 t = cC[i];
    return mk2(t.x, t.y);
}

// SU(2) apply: R = [[A, B], [-conj(B), conj(A)]], pre-negated components given.
__device__ __forceinline__ void apply_rot(p2 ar, p2 ai, p2 nai,
                                          p2 br, p2 nbr, p2 bi, p2 nbi,
                                          p2& ax, p2& ay, p2& bx, p2& by) {
    p2 nax = fma2(nbi, by, fma2(br,  bx, fma2(nai, ay, mul2(ar,  ax))));
    p2 nay = fma2(bi,  bx, fma2(br,  by, fma2(ai,  ax, mul2(ar,  ay))));
    p2 nbx = fma2(ai,  by, fma2(ar,  bx, fma2(nbi, ay, mul2(nbr, ax))));
    p2 nby = fma2(nai, bx, fma2(ar,  by, fma2(bi,  ax, mul2(nbr, ay))));
    ax = nax; ay = nay; bx = nbx; by = nby;
}

// G = R_m * RX(angle): SU(2) with components A=(gar,gai), B=(gbr,gbi)
__device__ __forceinline__ void buildG(int base, p2 c, p2 s,
                                       p2& gar, p2& gai, p2& gbr, p2& gbi) {
    p2 Mar = ldc(base + 0), Mai = ldc(base + 1), Mbr = ldc(base + 3),
       Mnbr = ldc(base + 4), Mbi = ldc(base + 5), Mnar = ldc(base + 7);
    gar = fma2(Mar, c, mul2(Mbi,  s));   // ar*c + bi*s
    gai = fma2(Mai, c, mul2(Mnbr, s));   // ai*c - br*s
    gbr = fma2(Mai, s, mul2(Mbr,  c));   // ai*s + br*c
    gbi = fma2(Mbi, c, mul2(Mnar, s));   // bi*c - ar*s
}

__global__ __launch_bounds__(TPB) void hybrid_qnn_kernel(
    const float4* __restrict__ x4, float4* __restrict__ out4, int B4)
{
    int i = blockIdx.x * TPB + threadIdx.x;
    if (i >= B4) return;

    // ---- 4 samples per thread: 2 independent packed chains ----
    p2 c0[2], s0[2], c1[2], s1[2];
#pragma unroll
    for (int ch = 0; ch < 2; ch++) {
        float4 xv = x4[2 * i + ch];
        p2 X0 = mk2(xv.x, xv.z);
        p2 X1 = mk2(xv.y, xv.w);

        float lo, hi;
        p2 h[4];
#pragma unroll
        for (int j = 0; j < 4; j++) {
            p2 t = fma2(ldc(2*j), X0, fma2(ldc(2*j+1), X1, ldc(8+j)));
            un2(t, lo, hi);
            h[j] = mk2(fast_tanh(lo), fast_tanh(hi));
        }
        p2 t0 = fma2(ldc(12), h[0], fma2(ldc(13), h[1], fma2(ldc(14), h[2], fma2(ldc(15), h[3], ldc(20)))));
        p2 t1 = fma2(ldc(16), h[0], fma2(ldc(17), h[1], fma2(ldc(18), h[2], fma2(ldc(19), h[3], ldc(21)))));

        float a0l, a0h, a1l, a1h;
        un2(t0, a0l, a0h); un2(t1, a1l, a1h);
        a0l = fast_tanh(a0l); a0h = fast_tanh(a0h);
        a1l = fast_tanh(a1l); a1h = fast_tanh(a1h);

        float sl, cl, sh, chh;
        __sincosf(0.5f * a0l, &sl, &cl); __sincosf(0.5f * a0h, &sh, &chh);
        c0[ch] = mk2(cl, chh); s0[ch] = mk2(sl, sh);
        __sincosf(0.5f * a1l, &sl, &cl); __sincosf(0.5f * a1h, &sh, &chh);
        c1[ch] = mk2(cl, chh); s1[ch] = mk2(sl, sh);
    }

    p2 s00x[2], s00y[2], s01x[2], s01y[2], s10x[2], s10y[2], s11x[2], s11y[2];

    // ---- layer 0 on |00>: state = CNOT-perm of (G0 col0) x (G1 col0) ----
#pragma unroll
    for (int ch = 0; ch < 2; ch++) {
        p2 a0r, a0i, b0r, b0i, a1r, a1i, b1r, b1i;
        buildG(25 + 0, c0[ch], s0[ch], a0r, a0i, b0r, b0i);
        buildG(25 + 8, c1[ch], s1[ch], a1r, a1i, b1r, b1i);
        p2 na0r = neg2(a0r), na0i = neg2(a0i), nb0r = neg2(b0r), nb0i = neg2(b0i);
        // pre-CNOT: t00=A0*A1, t01=-A0*conj(B1), t10=-conj(B0)*A1, t11=conj(B0)*conj(B1)
        // post-CNOT labels: s00=t00, s01=t10, s10=t11, s11=t01
        s00x[ch] = fma2(na0i, a1i, mul2(a0r, a1r));
        s00y[ch] = fma2(a0i,  a1r, mul2(a0r, a1i));
        s01x[ch] = fma2(nb0i, a1i, mul2(nb0r, a1r));
        s01y[ch] = fma2(b0i,  a1r, mul2(nb0r, a1i));
        s10x[ch] = fma2(nb0i, b1i, mul2(b0r,  b1r));
        s10y[ch] = fma2(nb0i, b1r, mul2(nb0r, b1i));
        s11x[ch] = fma2(na0i, b1i, mul2(na0r, b1r));
        s11y[ch] = fma2(na0i, b1r, mul2(a0r,  b1i));
    }

    // ---- layers 1..3: fused G = R*RX per wire ----
#pragma unroll
    for (int l = 1; l < NL; l++) {
#pragma unroll
        for (int ch = 0; ch < 2; ch++) {
            {   // wire 0 on pairs (s00,s10), (s01,s11)
                p2 gar, gai, gbr, gbi;
                buildG(25 + (l * 2 + 0) * 8, c0[ch], s0[ch], gar, gai, gbr, gbi);
                p2 ngai = neg2(gai), ngbr = neg2(gbr), ngbi = neg2(gbi);
                apply_rot(gar, gai, ngai, gbr, ngbr, gbi, ngbi,
                          s00x[ch], s00y[ch], s10x[ch], s10y[ch]);
                apply_rot(gar, gai, ngai, gbr, ngbr, gbi, ngbi,
                          s01x[ch], s01y[ch], s11x[ch], s11y[ch]);
            }
            {   // wire 1 on pairs (s00,s01), (s10,s11)
                p2 gar, gai, gbr, gbi;
                buildG(25 + (l * 2 + 1) * 8, c1[ch], s1[ch], gar, gai, gbr, gbi);
                p2 ngai = neg2(gai), ngbr = neg2(gbr), ngbi = neg2(gbi);
                apply_rot(gar, gai, ngai, gbr, ngbr, gbi, ngbi,
                          s00x[ch], s00y[ch], s01x[ch], s01y[ch]);
                apply_rot(gar, gai, ngai, gbr, ngbr, gbi, ngbi,
                          s10x[ch], s10y[ch], s11x[ch], s11y[ch]);
            }
            // CNOT(0,1): swap s10 <-> s11 ; CNOT(1,0): swap s01 <-> s11
            p2 tx = s10x[ch], ty = s10y[ch];
            s10x[ch] = s11x[ch]; s10y[ch] = s11y[ch]; s11x[ch] = tx; s11y[ch] = ty;
            tx = s01x[ch]; ty = s01y[ch];
            s01x[ch] = s11x[ch]; s01y[ch] = s11y[ch]; s11x[ch] = tx; s11y[ch] = ty;
        }
    }

    // ---- measurement; unitarity => q0 = p00+p01, q1 = p00+p10 ----
    float o[4];
#pragma unroll
    for (int ch = 0; ch < 2; ch++) {
        p2 m00 = fma2(s00y[ch], s00y[ch], mul2(s00x[ch], s00x[ch]));
        p2 q0 = fma2(s01y[ch], s01y[ch], fma2(s01x[ch], s01x[ch], m00));
        p2 q1 = fma2(s10y[ch], s10y[ch], fma2(s10x[ch], s10x[ch], m00));
        p2 y = fma2(ldc(22), q0, fma2(ldc(23), q1, ldc(24)));
        float yl, yh;
        un2(y, yl, yh);
        // sigmoid(y) = 0.5*tanh(y/2) + 0.5
        o[2*ch]   = fmaf(0.5f, fast_tanh(0.5f * yl), 0.5f);
        o[2*ch+1] = fmaf(0.5f, fast_tanh(0.5f * yh), 0.5f);
    }
    out4[i] = make_float4(o[0], o[1], o[2], o[3]);
}

extern "C" void kernel_launch(void* const* d_in, const int* in_sizes, int n_in,
                              void* d_out, int out_size) {
    const float4* x  = (const float4*)d_in[0];
    const float* w1  = (const float*)d_in[1];
    const float* b1  = (const float*)d_in[2];
    const float* w2  = (const float*)d_in[3];
    const float* b2  = (const float*)d_in[4];
    const float* qw  = (const float*)d_in[5];
    const float* pw  = (const float*)d_in[6];
    const float* pb  = (const float*)d_in[7];
    float4* out = (float4*)d_out;

    setup_kernel<<<1, 64>>>(w1, b1, w2, b2, qw, pw, pb);

    void* stage_ptr = nullptr;
    cudaGetSymbolAddress(&stage_ptr, gStage);
    cudaMemcpyToSymbolAsync(cC, stage_ptr, 89 * sizeof(float2), 0,
                            cudaMemcpyDeviceToDevice, 0);

    int B4 = in_sizes[0] / 8;  // four samples per thread
    int grid = (B4 + TPB - 1) / TPB;
    hybrid_qnn_kernel<<<grid, TPB>>>(x, out, B4);
}